// round 13
// baseline (speedup 1.0000x reference)
#include <cuda_runtime.h>
#include <cuda_fp16.h>
#include <math.h>
#include <cstdint>
#include <limits.h>

// ---------------------------------------------------------------------------
// JointCCSA via fp16 mma.sync (HMMA) Gram matrix, fp32 accumulate.
//   dist[i][j] = sqrt(max(sq_i + sq_j - 2 * X_i.X_j, 0))
//   sa_sum += dist           where y_i==y_j && ds_i!=ds_j   (unordered pairs)
//   s_sum  += max(0,1-dist)  where y_i!=y_j && ds_i!=ds_j && (y_i<y_j)==(ds_i<ds_j)
// Rows counting-sorted by (domain, class). Each CTA runs an EXACT dead-tile
// scan over its 128x128 pair metadata before loading anything: tiles with no
// contributing pair (same-domain, or cross-domain with all yi>yj) exit early.
// Mainloop: upper-tri tiles, 8 warps x (64x32), 3-stage cp.async ring.
// ---------------------------------------------------------------------------

#define MAX_BS 4096
#define MAX_D  512
#define TILE   128
#define KCHUNK 64
#define NBINS  16
#define ROWH   72          // halfs per smem row (64 data + 8 pad)
#define ROWB   (ROWH * 2)  // 144 bytes
#define TB     (TILE * ROWB)   // 18432 bytes per tile-stage
#define NSTAGE 3
#define OFF_B    (NSTAGE * TB)
#define OFF_META (2 * NSTAGE * TB)
#define SMEM_TOTAL (OFF_META + 6 * 512 + 64)

__device__ float  g_sq[MAX_BS];
__device__ __half g_h[MAX_BS * MAX_D];
__device__ int    g_y[MAX_BS];
__device__ int    g_d[MAX_BS];
__device__ int    g_perm[MAX_BS];
__device__ double g_sa_sum;
__device__ double g_s_sum;
__device__ unsigned int g_done;

__device__ __forceinline__ uint32_t smem_u32(const void* p) {
    uint32_t a;
    asm("{ .reg .u64 t; cvta.to.shared.u64 t, %1; cvt.u32.u64 %0, t; }" : "=r"(a) : "l"(p));
    return a;
}
__device__ __forceinline__ void cp16(uint32_t saddr, const void* g) {
    asm volatile("cp.async.cg.shared.global [%0], [%1], 16;" :: "r"(saddr), "l"(g));
}
__device__ __forceinline__ void ldmatrix_x4(uint32_t* r, uint32_t addr) {
    asm volatile("ldmatrix.sync.aligned.m8n8.x4.shared.b16 {%0,%1,%2,%3}, [%4];"
                 : "=r"(r[0]), "=r"(r[1]), "=r"(r[2]), "=r"(r[3]) : "r"(addr));
}
__device__ __forceinline__ void mma16816(float* c, const uint32_t* a,
                                         uint32_t b0, uint32_t b1) {
    asm volatile(
        "mma.sync.aligned.m16n8k16.row.col.f32.f16.f16.f32 "
        "{%0,%1,%2,%3}, {%4,%5,%6,%7}, {%8,%9}, {%0,%1,%2,%3};"
        : "+f"(c[0]), "+f"(c[1]), "+f"(c[2]), "+f"(c[3])
        : "r"(a[0]), "r"(a[1]), "r"(a[2]), "r"(a[3]), "r"(b0), "r"(b1));
}

// ---------------------------------------------------------------------------
// Kernel 0: fused counting sort by key (ds<<2)|y  (single block)
// ---------------------------------------------------------------------------
__global__ __launch_bounds__(1024) void sort_kernel(const int* __restrict__ ds,
                                                    const int* __restrict__ y,
                                                    int bs) {
    __shared__ int h[NBINS];
    __shared__ int off[NBINS];
    if (threadIdx.x < NBINS) h[threadIdx.x] = 0;
    __syncthreads();
    for (int i = threadIdx.x; i < bs; i += blockDim.x)
        atomicAdd(&h[((ds[i] << 2) | (y[i] & 3)) & (NBINS - 1)], 1);
    __syncthreads();
    if (threadIdx.x == 0) {
        int acc = 0;
        for (int b = 0; b < NBINS; b++) { off[b] = acc; acc += h[b]; }
        g_sa_sum = 0.0; g_s_sum = 0.0; g_done = 0u;
    }
    __syncthreads();
    for (int i = threadIdx.x; i < bs; i += blockDim.x) {
        int key = ((ds[i] << 2) | (y[i] & 3)) & (NBINS - 1);
        int pos = atomicAdd(&off[key], 1);
        g_perm[pos] = i;
    }
}

// ---------------------------------------------------------------------------
// Kernel 1: gather-permuted fp16 convert + exact fp32 row norms + metadata
// ---------------------------------------------------------------------------
__global__ __launch_bounds__(128) void prep_kernel(const float* __restrict__ X,
                                                   const int* __restrict__ ds,
                                                   const int* __restrict__ y,
                                                   int bs, int d) {
    const int p = blockIdx.x;                  // sorted position
    const int src = (p < bs) ? g_perm[p] : -1;
    float s = 0.f;
    if (d == MAX_D) {
        const int k = threadIdx.x * 4;
        float4 v = make_float4(0.f, 0.f, 0.f, 0.f);
        if (src >= 0) v = *(const float4*)(X + (size_t)src * MAX_D + k);
        __half2 h01 = __floats2half2_rn(v.x, v.y);
        __half2 h23 = __floats2half2_rn(v.z, v.w);
        *(uint2*)(g_h + (size_t)p * MAX_D + k) =
            make_uint2(*(uint32_t*)&h01, *(uint32_t*)&h23);
        s = v.x * v.x + v.y * v.y + v.z * v.z + v.w * v.w;
    } else {
        for (int k = threadIdx.x; k < MAX_D; k += blockDim.x) {
            float x = 0.f;
            if (src >= 0 && k < d) x = X[(size_t)src * d + k];
            g_h[(size_t)p * MAX_D + k] = __float2half_rn(x);
            s = fmaf(x, x, s);
        }
    }
    #pragma unroll
    for (int o = 16; o > 0; o >>= 1) s += __shfl_down_sync(0xffffffff, s, o);
    __shared__ float ws[4];
    int lane = threadIdx.x & 31, w = threadIdx.x >> 5;
    if (lane == 0) ws[w] = s;
    __syncthreads();
    if (threadIdx.x == 0) {
        g_sq[p] = ws[0] + ws[1] + ws[2] + ws[3];
        g_y[p] = (src >= 0) ? y[src]  : INT_MIN;
        g_d[p] = (src >= 0) ? ds[src] : INT_MIN;
    }
}

// ---------------------------------------------------------------------------
// Kernel 2: mma.sync tiled Gram + distance + masked reduction + finalize
// ---------------------------------------------------------------------------
__global__ __launch_bounds__(256) void pair_mma_kernel(
    const int* __restrict__ pnc,
    const int* __restrict__ pnd,
    float* __restrict__ out,
    int bs, int d, int nt, int nblocks)
{
    extern __shared__ char smem[];
    const uint32_t sbase = smem_u32(smem);
    float* isq_s = (float*)(smem + OFF_META);
    float* jsq_s = isq_s + TILE;
    int*   iy_s  = (int*)(jsq_s + TILE);
    int*   jy_s  = iy_s + TILE;
    int*   id_s  = jy_s + TILE;
    int*   jd_s  = id_s + TILE;
    float* red_s = (float*)(jd_s + TILE);

    const int tid = threadIdx.x;
    const int wid = tid >> 5, lane = tid & 31;

    // decode upper-tri (bi, bj)
    int t = blockIdx.x, bi = 0, rem = nt;
    while (t >= rem) { t -= rem; bi++; rem--; }
    const int bj = bi + t;
    const int row_i_base = bi * TILE;
    const int row_j_base = bj * TILE;
    const bool diag = (bi == bj);

    // metadata (from permuted arrays)
    if (tid < TILE) {
        int i = row_i_base + tid;
        int j = row_j_base + tid;
        bool oi = (i < bs), oj = (j < bs);
        isq_s[tid] = oi ? g_sq[i] : 0.f;
        iy_s[tid]  = oi ? g_y[i] : INT_MIN;
        id_s[tid]  = oi ? g_d[i] : INT_MIN;
        jsq_s[tid] = oj ? g_sq[j] : 0.f;
        jy_s[tid]  = oj ? g_y[j] : INT_MIN;
        jd_s[tid]  = oj ? g_d[j] : INT_MIN;
    }
    __syncthreads();

    // ---- exact dead-tile scan: does ANY pair in this tile contribute?
    {
        int alive = 0;
        const int imax = min(TILE, bs - row_i_base);
        const int jmax = min(TILE, bs - row_j_base);
        for (int l = tid; l < TILE * TILE; l += 256) {
            const int il = l >> 7, jl = l & 127;
            if (il >= imax || jl >= jmax) continue;
            if (diag && jl <= il) continue;
            const int di = id_s[il], dj = jd_s[jl];
            if (di == dj) continue;
            const int yi = iy_s[il], yj = jy_s[jl];
            if (yi == yj || ((yi < yj) == (di < dj))) { alive = 1; break; }
        }
        if (!__syncthreads_or(alive)) {
            if (tid == 0) {
                __threadfence();
                unsigned int prev = atomicAdd(&g_done, 1u);
                if (prev == (unsigned int)(nblocks - 1)) {
                    int nc = pnc ? *pnc : 4;
                    int nd = pnd ? *pnd : 3;
                    int dpairs = nd * (nd - 1) / 2;
                    double n_sa = (double)nc * dpairs;
                    double n_s  = (double)(nc * (nc - 1) / 2) * dpairs;
                    out[0] = (float)(0.5 * g_sa_sum / n_sa);
                    out[1] = (float)(0.5 * g_s_sum  / n_s);
                }
            }
            return;
        }
    }

    const int nchunks = (d + KCHUNK - 1) / KCHUNK;   // 8 for d=512

    auto issue_chunk = [&](int c) {
        const uint32_t st = (uint32_t)(c % NSTAGE) * TB;
        const int k0 = c * KCHUNK;
        #pragma unroll
        for (int it = 0; it < 4; it++) {
            int lin = tid + 256 * it;      // 0..1023
            int r   = lin >> 3;
            int cb  = lin & 7;
            uint32_t so = (uint32_t)(r * ROWB + cb * 16);
            cp16(sbase + st + so,
                 g_h + (size_t)(row_i_base + r) * MAX_D + k0 + cb * 8);
            cp16(sbase + OFF_B + st + so,
                 g_h + (size_t)(row_j_base + r) * MAX_D + k0 + cb * 8);
        }
        asm volatile("cp.async.commit_group;" ::: "memory");
    };

    const int warp_m = wid & 1;
    const int warp_n = wid >> 1;
    const int la_r = (lane & 7) + ((lane >> 3) & 1) * 8;
    const int la_k = ((lane >> 4) & 1) * 8;
    const int lb_n = (lane & 7) + ((lane >> 4) & 1) * 8;
    const int lb_k = ((lane >> 3) & 1) * 8;
    const uint32_t a_lane = (uint32_t)((warp_m * 64 + la_r) * ROWB + la_k * 2);
    const uint32_t b_lane = (uint32_t)((warp_n * 32 + lb_n) * ROWB + lb_k * 2);

    uint32_t af[2][4][4];
    uint32_t bf[2][2][4];
    float c[4][4][4];
    #pragma unroll
    for (int mt = 0; mt < 4; mt++)
        #pragma unroll
        for (int ntl = 0; ntl < 4; ntl++)
            #pragma unroll
            for (int r = 0; r < 4; r++) c[mt][ntl][r] = 0.f;

    auto load_frags = [&](int p, uint32_t stage_off, int ks) {
        const uint32_t ab = sbase + stage_off + a_lane + (uint32_t)(ks * 32);
        const uint32_t bb = sbase + OFF_B + stage_off + b_lane + (uint32_t)(ks * 32);
        #pragma unroll
        for (int mt = 0; mt < 4; mt++)
            ldmatrix_x4(af[p][mt], ab + (uint32_t)(mt * 16 * ROWB));
        #pragma unroll
        for (int np = 0; np < 2; np++)
            ldmatrix_x4(bf[p][np], bb + (uint32_t)(np * 16 * ROWB));
    };
    auto mma_all = [&](int p) {
        #pragma unroll
        for (int mt = 0; mt < 4; mt++)
            #pragma unroll
            for (int ntl = 0; ntl < 4; ntl++)
                mma16816(c[mt][ntl], af[p][mt],
                         bf[p][ntl >> 1][(ntl & 1) * 2],
                         bf[p][ntl >> 1][(ntl & 1) * 2 + 1]);
    };

    // prologue: fill 2 stages
    issue_chunk(0);
    if (nchunks > 1) issue_chunk(1);
    asm volatile("cp.async.wait_group 1;" ::: "memory");
    __syncthreads();
    load_frags(0, 0u, 0);

    for (int ck = 0; ck < nchunks; ck++) {
        if (ck + 2 < nchunks) issue_chunk(ck + 2);
        const uint32_t st = (uint32_t)(ck % NSTAGE) * TB;
        load_frags(1, st, 1); mma_all(0);
        load_frags(0, st, 2); mma_all(1);
        load_frags(1, st, 3); mma_all(0);
        if (ck + 1 < nchunks) {
            asm volatile("cp.async.wait_group 1;" ::: "memory");
            __syncthreads();
            load_frags(0, (uint32_t)((ck + 1) % NSTAGE) * TB, 0);
            mma_all(1);
        } else {
            mma_all(1);
        }
    }

    // ---- epilogue: distances + masks from register fragments ----
    const int tr = lane >> 2;
    const int tc = lane & 3;
    float sa_acc = 0.f, s_acc = 0.f;

    #pragma unroll
    for (int mt = 0; mt < 4; mt++) {
        #pragma unroll
        for (int rh = 0; rh < 2; rh++) {
            const int i_local = warp_m * 64 + mt * 16 + tr + rh * 8;
            const int i = row_i_base + i_local;
            if (i >= bs) continue;
            const float sqi = isq_s[i_local];
            const int yi = iy_s[i_local], di = id_s[i_local];
            #pragma unroll
            for (int ntl = 0; ntl < 4; ntl++) {
                #pragma unroll
                for (int cpair = 0; cpair < 2; cpair++) {
                    const int j_local = warp_n * 32 + ntl * 8 + tc * 2 + cpair;
                    const int j = row_j_base + j_local;
                    if (j >= bs) continue;
                    if (diag && j_local <= i_local) continue;
                    const float dot = c[mt][ntl][rh * 2 + cpair];
                    const float d2 = sqi + jsq_s[j_local] - 2.f * dot;
                    const float dist = sqrtf(fmaxf(d2, 0.f));
                    const int yj = jy_s[j_local], dj = jd_s[j_local];
                    const bool ddiff = (di != dj);
                    if (ddiff && yi == yj) sa_acc += dist;
                    if (ddiff && yi != yj && ((yi < yj) == (di < dj)))
                        s_acc += fmaxf(0.f, 1.f - dist);
                }
            }
        }
    }

    // block reduction + global accumulate + fused finalize
    #pragma unroll
    for (int o = 16; o > 0; o >>= 1) {
        sa_acc += __shfl_down_sync(0xffffffff, sa_acc, o);
        s_acc  += __shfl_down_sync(0xffffffff, s_acc,  o);
    }
    if (lane == 0) { red_s[wid] = sa_acc; red_s[8 + wid] = s_acc; }
    __syncthreads();
    if (tid == 0) {
        float tsa = 0.f, tss = 0.f;
        #pragma unroll
        for (int k = 0; k < 8; k++) { tsa += red_s[k]; tss += red_s[8 + k]; }
        atomicAdd(&g_sa_sum, (double)tsa);
        atomicAdd(&g_s_sum,  (double)tss);
        __threadfence();
        unsigned int prev = atomicAdd(&g_done, 1u);
        if (prev == (unsigned int)(nblocks - 1)) {
            int nc = pnc ? *pnc : 4;
            int nd = pnd ? *pnd : 3;
            int dpairs = nd * (nd - 1) / 2;
            double n_sa = (double)nc * dpairs;
            double n_s  = (double)(nc * (nc - 1) / 2) * dpairs;
            out[0] = (float)(0.5 * g_sa_sum / n_sa);
            out[1] = (float)(0.5 * g_s_sum  / n_s);
        }
    }
}

// ---------------------------------------------------------------------------
extern "C" void kernel_launch(void* const* d_in, const int* in_sizes, int n_in,
                              void* d_out, int out_size) {
    const float* X  = (const float*)d_in[0];
    const int*   ds = (const int*)d_in[1];
    const int*   y  = (const int*)d_in[2];
    const int* pnc = (n_in >= 5) ? (const int*)d_in[3] : nullptr;
    const int* pnd = (n_in >= 5) ? (const int*)d_in[4] : nullptr;

    int bs = in_sizes[1];
    int d  = in_sizes[0] / bs;
    if (bs > MAX_BS) bs = MAX_BS;   // dataset shape is 4096x512
    if (d  > MAX_D)  d  = MAX_D;
    int nt = (bs + TILE - 1) / TILE;
    int nblocks = nt * (nt + 1) / 2;

    cudaFuncSetAttribute(pair_mma_kernel,
                         cudaFuncAttributeMaxDynamicSharedMemorySize, SMEM_TOTAL);

    sort_kernel<<<1, 1024>>>(ds, y, bs);
    prep_kernel<<<MAX_BS, 128>>>(X, ds, y, bs, d);
    pair_mma_kernel<<<nblocks, 256, SMEM_TOTAL>>>(pnc, pnd, (float*)d_out,
                                                  bs, d, nt, nblocks);
}

// round 16
// speedup vs baseline: 1.8476x; 1.8476x over previous
#include <cuda_runtime.h>
#include <cuda_fp16.h>
#include <math.h>
#include <cstdint>
#include <limits.h>

// ---------------------------------------------------------------------------
// JointCCSA via fp16 mma.sync (HMMA) Gram matrix, fp32 accumulate.
//   dist[i][j] = sqrt(max(sq_i + sq_j - 2 * X_i.X_j, 0))
//   sa_sum += dist           where y_i==y_j && ds_i!=ds_j   (unordered pairs)
//   s_sum  += max(0,1-dist)  where y_i!=y_j && ds_i!=ds_j && (y_i<y_j)==(ds_i<ds_j)
// Rows counting-sorted by key (ds<<2)|y (domain major, class minor).
// Each CTA does an O(1) exact deadness test via 32-bit key-presence masks:
// dead tiles (same-domain, or cross-domain with all i-classes > j-classes)
// exit before any data load. Mainloop: upper-tri 128x128 tiles, 8 warps x
// (64x32), 3-stage cp.async ring (R12's proven config).
// ---------------------------------------------------------------------------

#define MAX_BS 4096
#define MAX_D  512
#define TILE   128
#define KCHUNK 64
#define NBINS  32
#define ROWH   72          // halfs per smem row (64 data + 8 pad)
#define ROWB   (ROWH * 2)  // 144 bytes
#define TB     (TILE * ROWB)   // 18432 bytes per tile-stage
#define NSTAGE 3
#define OFF_B    (NSTAGE * TB)
#define OFF_META (2 * NSTAGE * TB)
#define SMEM_TOTAL (OFF_META + 6 * 512 + 64)

__device__ float  g_sq[MAX_BS];
__device__ __half g_h[MAX_BS * MAX_D];
__device__ int    g_y[MAX_BS];
__device__ int    g_d[MAX_BS];
__device__ int    g_off[NBINS];
__device__ int    g_perm[MAX_BS];
__device__ double g_sa_sum;
__device__ double g_s_sum;
__device__ unsigned int g_done;

__device__ __forceinline__ uint32_t smem_u32(const void* p) {
    uint32_t a;
    asm("{ .reg .u64 t; cvta.to.shared.u64 t, %1; cvt.u32.u64 %0, t; }" : "=r"(a) : "l"(p));
    return a;
}
__device__ __forceinline__ void cp16(uint32_t saddr, const void* g) {
    asm volatile("cp.async.cg.shared.global [%0], [%1], 16;" :: "r"(saddr), "l"(g));
}
__device__ __forceinline__ void ldmatrix_x4(uint32_t* r, uint32_t addr) {
    asm volatile("ldmatrix.sync.aligned.m8n8.x4.shared.b16 {%0,%1,%2,%3}, [%4];"
                 : "=r"(r[0]), "=r"(r[1]), "=r"(r[2]), "=r"(r[3]) : "r"(addr));
}
__device__ __forceinline__ void mma16816(float* c, const uint32_t* a,
                                         uint32_t b0, uint32_t b1) {
    asm volatile(
        "mma.sync.aligned.m16n8k16.row.col.f32.f16.f16.f32 "
        "{%0,%1,%2,%3}, {%4,%5,%6,%7}, {%8,%9}, {%0,%1,%2,%3};"
        : "+f"(c[0]), "+f"(c[1]), "+f"(c[2]), "+f"(c[3])
        : "r"(a[0]), "r"(a[1]), "r"(a[2]), "r"(a[3]), "r"(b0), "r"(b1));
}

// key: (d<<2)|y if in range [0,8)x[0,4); else 31 (sentinel -> force alive)
__device__ __forceinline__ int row_key(int d, int y) {
    if (d < 0 || d > 7 || y < 0 || y > 3) return 31;
    int k = (d << 2) | y;
    return (k < 31) ? k : 31;
}

// ---------------------------------------------------------------------------
// Kernel 0a: histogram over (ds,y) bins + exclusive scan + accumulator init
// ---------------------------------------------------------------------------
__global__ void hist_kernel(const int* __restrict__ ds,
                            const int* __restrict__ y, int bs) {
    __shared__ int h[NBINS];
    if (threadIdx.x < NBINS) h[threadIdx.x] = 0;
    __syncthreads();
    for (int i = threadIdx.x; i < bs; i += blockDim.x)
        atomicAdd(&h[((ds[i] << 2) | (y[i] & 3)) & (NBINS - 1)], 1);
    __syncthreads();
    if (threadIdx.x == 0) {
        int acc = 0;
        for (int b = 0; b < NBINS; b++) { g_off[b] = acc; acc += h[b]; }
        g_sa_sum = 0.0; g_s_sum = 0.0; g_done = 0u;
    }
}

// ---------------------------------------------------------------------------
// Kernel 0b: scatter rows into (domain, class)-sorted order
// ---------------------------------------------------------------------------
__global__ void scatter_kernel(const int* __restrict__ ds,
                               const int* __restrict__ y, int bs) {
    int i = blockIdx.x * blockDim.x + threadIdx.x;
    if (i < bs) {
        int pos = atomicAdd(&g_off[((ds[i] << 2) | (y[i] & 3)) & (NBINS - 1)], 1);
        g_perm[pos] = i;
    }
}

// ---------------------------------------------------------------------------
// Kernel 1: gather-permuted fp16 convert + exact fp32 row norms + metadata
// warp-per-row: 256 blocks x 512 threads (16 warps), lane does 4 float4
// ---------------------------------------------------------------------------
__global__ __launch_bounds__(512) void prep_kernel(const float* __restrict__ X,
                                                   const int* __restrict__ ds,
                                                   const int* __restrict__ y,
                                                   int bs, int d) {
    const int lane = threadIdx.x & 31;
    const int p = blockIdx.x * 16 + (threadIdx.x >> 5);   // sorted position
    if (p >= MAX_BS) return;
    const int src = (p < bs) ? g_perm[p] : -1;
    float s = 0.f;
    if (d == MAX_D) {
        #pragma unroll
        for (int c = 0; c < 4; c++) {
            const int k = (lane + c * 32) * 4;
            float4 v = make_float4(0.f, 0.f, 0.f, 0.f);
            if (src >= 0) v = *(const float4*)(X + (size_t)src * MAX_D + k);
            __half2 h01 = __floats2half2_rn(v.x, v.y);
            __half2 h23 = __floats2half2_rn(v.z, v.w);
            *(uint2*)(g_h + (size_t)p * MAX_D + k) =
                make_uint2(*(uint32_t*)&h01, *(uint32_t*)&h23);
            s += v.x * v.x + v.y * v.y + v.z * v.z + v.w * v.w;
        }
    } else {
        for (int k = lane; k < MAX_D; k += 32) {
            float x = 0.f;
            if (src >= 0 && k < d) x = X[(size_t)src * d + k];
            g_h[(size_t)p * MAX_D + k] = __float2half_rn(x);
            s = fmaf(x, x, s);
        }
    }
    #pragma unroll
    for (int o = 16; o > 0; o >>= 1) s += __shfl_down_sync(0xffffffff, s, o);
    if (lane == 0) {
        g_sq[p] = s;
        g_y[p] = (src >= 0) ? y[src]  : INT_MIN;
        g_d[p] = (src >= 0) ? ds[src] : INT_MIN;
    }
}

// ---------------------------------------------------------------------------
// Kernel 2: mma.sync tiled Gram + distance + masked reduction + finalize
// ---------------------------------------------------------------------------
__global__ __launch_bounds__(256) void pair_mma_kernel(
    const int* __restrict__ pnc,
    const int* __restrict__ pnd,
    float* __restrict__ out,
    int bs, int d, int nt, int nblocks)
{
    extern __shared__ char smem[];
    const uint32_t sbase = smem_u32(smem);
    float* isq_s = (float*)(smem + OFF_META);
    float* jsq_s = isq_s + TILE;
    int*   iy_s  = (int*)(jsq_s + TILE);
    int*   jy_s  = iy_s + TILE;
    int*   id_s  = jy_s + TILE;
    int*   jd_s  = id_s + TILE;
    float* red_s = (float*)(jd_s + TILE);
    unsigned int* mask_s = (unsigned int*)(red_s + 16);   // [0]=imask [1]=jmask

    const int tid = threadIdx.x;
    const int wid = tid >> 5, lane = tid & 31;

    // decode upper-tri (bi, bj)
    int t = blockIdx.x, bi = 0, rem = nt;
    while (t >= rem) { t -= rem; bi++; rem--; }
    const int bj = bi + t;
    const int row_i_base = bi * TILE;
    const int row_j_base = bj * TILE;
    const bool diag = (bi == bj);

    if (tid < 2) mask_s[tid] = 0u;

    // metadata (from permuted arrays)
    if (tid < TILE) {
        int i = row_i_base + tid;
        bool oi = (i < bs);
        isq_s[tid] = oi ? g_sq[i] : 0.f;
        int yi = oi ? g_y[i] : INT_MIN;
        int di = oi ? g_d[i] : INT_MIN;
        iy_s[tid] = yi; id_s[tid] = di;
        if (oi) atomicOr(&mask_s[0], 1u << row_key(di, yi));
    } else {
        int j = row_j_base + (tid - TILE);
        bool oj = (j < bs);
        jsq_s[tid - TILE] = oj ? g_sq[j] : 0.f;
        int yj = oj ? g_y[j] : INT_MIN;
        int dj = oj ? g_d[j] : INT_MIN;
        jy_s[tid - TILE] = yj; jd_s[tid - TILE] = dj;
        if (oj) atomicOr(&mask_s[1], 1u << row_key(dj, yj));
    }
    __syncthreads();

    // ---- O(1) exact deadness test over key combos
    {
        const unsigned int imask = mask_s[0];
        const unsigned int jmask = mask_s[1];
        int alive = 0;
        if (((imask | jmask) >> 31) & 1u) {
            alive = 1;                       // out-of-range labels: be safe
        } else {
            #pragma unroll
            for (int q = 0; q < 4; q++) {
                const int k = tid + q * 256;     // 0..1023
                const int ki = k >> 5, kj = k & 31;
                if (!((imask >> ki) & 1u) || !((jmask >> kj) & 1u)) continue;
                if (diag && ki >= kj) continue;  // sorted: i-row precedes j-row
                const int di = ki >> 2, yi = ki & 3;
                const int dj = kj >> 2, yj = kj & 3;
                if (di != dj && (yi == yj || ((yi < yj) == (di < dj)))) alive = 1;
            }
        }
        if (!__syncthreads_or(alive)) {
            if (tid == 0) {
                __threadfence();
                unsigned int prev = atomicAdd(&g_done, 1u);
                if (prev == (unsigned int)(nblocks - 1)) {
                    int nc = pnc ? *pnc : 4;
                    int nd = pnd ? *pnd : 3;
                    int dpairs = nd * (nd - 1) / 2;
                    double n_sa = (double)nc * dpairs;
                    double n_s  = (double)(nc * (nc - 1) / 2) * dpairs;
                    out[0] = (float)(0.5 * g_sa_sum / n_sa);
                    out[1] = (float)(0.5 * g_s_sum  / n_s);
                }
            }
            return;
        }
    }

    const int nchunks = (d + KCHUNK - 1) / KCHUNK;   // 8 for d=512

    auto issue_chunk = [&](int c) {
        const uint32_t st = (uint32_t)(c % NSTAGE) * TB;
        const int k0 = c * KCHUNK;
        #pragma unroll
        for (int it = 0; it < 4; it++) {
            int lin = tid + 256 * it;      // 0..1023
            int r   = lin >> 3;
            int cb  = lin & 7;
            uint32_t so = (uint32_t)(r * ROWB + cb * 16);
            cp16(sbase + st + so,
                 g_h + (size_t)(row_i_base + r) * MAX_D + k0 + cb * 8);
            cp16(sbase + OFF_B + st + so,
                 g_h + (size_t)(row_j_base + r) * MAX_D + k0 + cb * 8);
        }
        asm volatile("cp.async.commit_group;" ::: "memory");
    };

    const int warp_m = wid & 1;
    const int warp_n = wid >> 1;
    const int la_r = (lane & 7) + ((lane >> 3) & 1) * 8;
    const int la_k = ((lane >> 4) & 1) * 8;
    const int lb_n = (lane & 7) + ((lane >> 4) & 1) * 8;
    const int lb_k = ((lane >> 3) & 1) * 8;
    const uint32_t a_lane = (uint32_t)((warp_m * 64 + la_r) * ROWB + la_k * 2);
    const uint32_t b_lane = (uint32_t)((warp_n * 32 + lb_n) * ROWB + lb_k * 2);

    uint32_t af[2][4][4];
    uint32_t bf[2][2][4];
    float c[4][4][4];
    #pragma unroll
    for (int mt = 0; mt < 4; mt++)
        #pragma unroll
        for (int ntl = 0; ntl < 4; ntl++)
            #pragma unroll
            for (int r = 0; r < 4; r++) c[mt][ntl][r] = 0.f;

    auto load_frags = [&](int p, uint32_t stage_off, int ks) {
        const uint32_t ab = sbase + stage_off + a_lane + (uint32_t)(ks * 32);
        const uint32_t bb = sbase + OFF_B + stage_off + b_lane + (uint32_t)(ks * 32);
        #pragma unroll
        for (int mt = 0; mt < 4; mt++)
            ldmatrix_x4(af[p][mt], ab + (uint32_t)(mt * 16 * ROWB));
        #pragma unroll
        for (int np = 0; np < 2; np++)
            ldmatrix_x4(bf[p][np], bb + (uint32_t)(np * 16 * ROWB));
    };
    auto mma_all = [&](int p) {
        #pragma unroll
        for (int mt = 0; mt < 4; mt++)
            #pragma unroll
            for (int ntl = 0; ntl < 4; ntl++)
                mma16816(c[mt][ntl], af[p][mt],
                         bf[p][ntl >> 1][(ntl & 1) * 2],
                         bf[p][ntl >> 1][(ntl & 1) * 2 + 1]);
    };

    // prologue: fill 2 stages
    issue_chunk(0);
    if (nchunks > 1) issue_chunk(1);
    asm volatile("cp.async.wait_group 1;" ::: "memory");
    __syncthreads();
    load_frags(0, 0u, 0);

    for (int ck = 0; ck < nchunks; ck++) {
        if (ck + 2 < nchunks) issue_chunk(ck + 2);
        const uint32_t st = (uint32_t)(ck % NSTAGE) * TB;
        load_frags(1, st, 1); mma_all(0);
        load_frags(0, st, 2); mma_all(1);
        load_frags(1, st, 3); mma_all(0);
        if (ck + 1 < nchunks) {
            asm volatile("cp.async.wait_group 1;" ::: "memory");
            __syncthreads();
            load_frags(0, (uint32_t)((ck + 1) % NSTAGE) * TB, 0);
            mma_all(1);
        } else {
            mma_all(1);
        }
    }

    // ---- epilogue: distances + masks from register fragments ----
    const int tr = lane >> 2;
    const int tc = lane & 3;
    float sa_acc = 0.f, s_acc = 0.f;

    #pragma unroll
    for (int mt = 0; mt < 4; mt++) {
        #pragma unroll
        for (int rh = 0; rh < 2; rh++) {
            const int i_local = warp_m * 64 + mt * 16 + tr + rh * 8;
            const int i = row_i_base + i_local;
            if (i >= bs) continue;
            const float sqi = isq_s[i_local];
            const int yi = iy_s[i_local], di = id_s[i_local];
            #pragma unroll
            for (int ntl = 0; ntl < 4; ntl++) {
                #pragma unroll
                for (int cpair = 0; cpair < 2; cpair++) {
                    const int j_local = warp_n * 32 + ntl * 8 + tc * 2 + cpair;
                    const int j = row_j_base + j_local;
                    if (j >= bs) continue;
                    if (diag && j_local <= i_local) continue;
                    const float dot = c[mt][ntl][rh * 2 + cpair];
                    const float d2 = sqi + jsq_s[j_local] - 2.f * dot;
                    const float dist = sqrtf(fmaxf(d2, 0.f));
                    const int yj = jy_s[j_local], dj = jd_s[j_local];
                    const bool ddiff = (di != dj);
                    if (ddiff && yi == yj) sa_acc += dist;
                    if (ddiff && yi != yj && ((yi < yj) == (di < dj)))
                        s_acc += fmaxf(0.f, 1.f - dist);
                }
            }
        }
    }

    // block reduction + global accumulate + fused finalize
    #pragma unroll
    for (int o = 16; o > 0; o >>= 1) {
        sa_acc += __shfl_down_sync(0xffffffff, sa_acc, o);
        s_acc  += __shfl_down_sync(0xffffffff, s_acc,  o);
    }
    if (lane == 0) { red_s[wid] = sa_acc; red_s[8 + wid] = s_acc; }
    __syncthreads();
    if (tid == 0) {
        float tsa = 0.f, tss = 0.f;
        #pragma unroll
        for (int k = 0; k < 8; k++) { tsa += red_s[k]; tss += red_s[8 + k]; }
        atomicAdd(&g_sa_sum, (double)tsa);
        atomicAdd(&g_s_sum,  (double)tss);
        __threadfence();
        unsigned int prev = atomicAdd(&g_done, 1u);
        if (prev == (unsigned int)(nblocks - 1)) {
            int nc = pnc ? *pnc : 4;
            int nd = pnd ? *pnd : 3;
            int dpairs = nd * (nd - 1) / 2;
            double n_sa = (double)nc * dpairs;
            double n_s  = (double)(nc * (nc - 1) / 2) * dpairs;
            out[0] = (float)(0.5 * g_sa_sum / n_sa);
            out[1] = (float)(0.5 * g_s_sum  / n_s);
        }
    }
}

// ---------------------------------------------------------------------------
extern "C" void kernel_launch(void* const* d_in, const int* in_sizes, int n_in,
                              void* d_out, int out_size) {
    const float* X  = (const float*)d_in[0];
    const int*   ds = (const int*)d_in[1];
    const int*   y  = (const int*)d_in[2];
    const int* pnc = (n_in >= 5) ? (const int*)d_in[3] : nullptr;
    const int* pnd = (n_in >= 5) ? (const int*)d_in[4] : nullptr;

    int bs = in_sizes[1];
    int d  = in_sizes[0] / bs;
    if (bs > MAX_BS) bs = MAX_BS;   // dataset shape is 4096x512
    if (d  > MAX_D)  d  = MAX_D;
    int nt = (bs + TILE - 1) / TILE;
    int nblocks = nt * (nt + 1) / 2;

    cudaFuncSetAttribute(pair_mma_kernel,
                         cudaFuncAttributeMaxDynamicSharedMemorySize, SMEM_TOTAL);

    hist_kernel<<<1, 256>>>(ds, y, bs);
    scatter_kernel<<<(bs + 255) / 256, 256>>>(ds, y, bs);
    prep_kernel<<<(MAX_BS + 15) / 16, 512>>>(X, ds, y, bs, d);
    pair_mma_kernel<<<nblocks, 256, SMEM_TOTAL>>>(pnc, pnd, (float*)d_out,
                                                  bs, d, nt, nblocks);
}